// round 12
// baseline (speedup 1.0000x reference)
#include <cuda_runtime.h>
#include <cuda_bf16.h>
#include <cuda_fp16.h>

#define N0 8192
#define N1 4096
#define N2 2048
#define STEPS 100
#define INF1 0.28f
#define INF2 0.20f
#define WSCALE 4096.0f
#define INV_WSCALE (1.0f / 4096.0f)

// transpose partial chunks: 32 rows each
#define CH0 256   // 8192 / 32
#define CH1 128   // 4096 / 32

// ---------------- scratch (device globals; no allocation in kernel_launch) ----
__device__ __align__(16) unsigned char g_W0f8[(size_t)N0 * N1];   // 32 MB, e4m3 = W0 * 4096
__device__ __align__(16) unsigned char g_W1f8[(size_t)N1 * N2];   // 8 MB,  e4m3 = W1 * 4096
__device__ float g_e0[N0];
__device__ float g_e1[N1];
__device__ float g_ract1[N1], g_rout1[N1];
__device__ float g_ract2[N2], g_rout2[N2];
__device__ __align__(16) __half g_rh1[N1];          // f16 copy of r_out1
__device__ __align__(16) __half g_rh2[N2];          // f16 copy of r_out2
__device__ float g_pbu1[(size_t)CH0 * N1];          // 4 MB
__device__ float g_pbu2[(size_t)CH1 * N2];          // 1 MB

__device__ __forceinline__ float sigm3(float x) {
    // sigmoid(x - 3)
    return 1.0f / (1.0f + expf(3.0f - x));
}

// pack 4 floats -> 4 e4m3 bytes (byte0 = v.x ... byte3 = v.w)
__device__ __forceinline__ unsigned pack4_e4m3(float4 v) {
    unsigned short lo, hi;
    asm("cvt.rn.satfinite.e4m3x2.f32 %0, %1, %2;" : "=h"(lo) : "f"(v.y), "f"(v.x));
    asm("cvt.rn.satfinite.e4m3x2.f32 %0, %1, %2;" : "=h"(hi) : "f"(v.w), "f"(v.z));
    return (unsigned)lo | ((unsigned)hi << 16);
}

// decode u32 (4 e4m3) -> two __half2 (a = vals 0,1 ; b = vals 2,3)
__device__ __forceinline__ void u32_to_2h2(unsigned u, __half2& a, __half2& b) {
    unsigned ra, rb;
    asm("{\n\t"
        ".reg .b16 lo, hi;\n\t"
        "mov.b32 {lo, hi}, %2;\n\t"
        "cvt.rn.f16x2.e4m3x2 %0, lo;\n\t"
        "cvt.rn.f16x2.e4m3x2 %1, hi;\n\t"
        "}"
        : "=r"(ra), "=r"(rb) : "r"(u));
    a = *reinterpret_cast<__half2*>(&ra);
    b = *reinterpret_cast<__half2*>(&rb);
}

__device__ __forceinline__ __half2 as_h2(unsigned u) {
    return *reinterpret_cast<__half2*>(&u);
}

// ---------------- one-time per-launch setup ----------------------------------
__global__ void k_convert(const float* __restrict__ W0, const float* __restrict__ W1) {
    size_t i = (size_t)blockIdx.x * blockDim.x + threadIdx.x;
    const size_t n0q = (size_t)N0 * N1 / 4;
    const size_t n1q = (size_t)N1 * N2 / 4;
    if (i < n0q) {
        float4 v = __ldg((const float4*)W0 + i);
        v.x *= WSCALE; v.y *= WSCALE; v.z *= WSCALE; v.w *= WSCALE;
        reinterpret_cast<unsigned*>(g_W0f8)[i] = pack4_e4m3(v);
    } else if (i < n0q + n1q) {
        size_t j = i - n0q;
        float4 v = __ldg((const float4*)W1 + j);
        v.x *= WSCALE; v.y *= WSCALE; v.z *= WSCALE; v.w *= WSCALE;
        reinterpret_cast<unsigned*>(g_W1f8)[j] = pack4_e4m3(v);
    }
}

__global__ void k_init() {
    int j = blockIdx.x * blockDim.x + threadIdx.x;
    float r0 = sigm3(-2.0f);
    if (j < N1) {
        g_ract1[j] = -2.0f;
        g_rout1[j] = r0;
        g_rh1[j] = __float2half(r0);
    } else if (j < N1 + N2) {
        int k = j - N1;
        g_ract2[k] = -2.0f;
        g_rout2[k] = r0;
        g_rh2[k] = __float2half(r0);
    }
}

// dot of one fp8 uint4 (16 w) against 16 r halves (2 uint4 of __half2), f16 chain
__device__ __forceinline__ void dot16_f8(uint4 wq, uint4 rq0, uint4 rq1, float& acc) {
    __half2 h = __float2half2_rn(0.0f);
    __half2 a, b;
    u32_to_2h2(wq.x, a, b);
    h = __hfma2(a, as_h2(rq0.x), h);
    h = __hfma2(b, as_h2(rq0.y), h);
    u32_to_2h2(wq.y, a, b);
    h = __hfma2(a, as_h2(rq0.z), h);
    h = __hfma2(b, as_h2(rq0.w), h);
    u32_to_2h2(wq.z, a, b);
    h = __hfma2(a, as_h2(rq1.x), h);
    h = __hfma2(b, as_h2(rq1.y), h);
    u32_to_2h2(wq.w, a, b);
    h = __hfma2(a, as_h2(rq1.z), h);
    h = __hfma2(b, as_h2(rq1.w), h);
    float2 f = __half22float2(h);
    acc += f.x + f.y;
}

// ---------------- per-step K1: forward matvecs --------------------------------
// e0 = frame - W0 @ r1 ;  e1 = r1 - W1 @ r2
// 1 row per warp. Blocks [0,1024): W0 (8192 warps -> 8192 rows).
// Blocks [1024,1536): W1 (4096 warps -> 4096 rows).
__global__ void __launch_bounds__(256) k_forward(const float* __restrict__ frame) {
    int tid = threadIdx.x, lane = tid & 31, warp = tid >> 5;
    int b = blockIdx.x;
    if (b < 1024) {
        int row = b * 8 + warp;              // 0..8191
        const uint4* w0 = (const uint4*)(g_W0f8 + (size_t)row * N1);
        const uint4* rp = (const uint4*)g_rh1;   // 512 uint4 = 4096 halves
        float a0 = 0.f;
        // 256 uint4 per row (16 fp8 each), 8 iters per lane
        #pragma unroll
        for (int i = 0; i < 8; i++) {
            int c = lane + i * 32;
            uint4 rq0 = __ldg(rp + 2 * c);
            uint4 rq1 = __ldg(rp + 2 * c + 1);
            dot16_f8(__ldg(w0 + c), rq0, rq1, a0);
        }
        #pragma unroll
        for (int o = 16; o; o >>= 1) a0 += __shfl_xor_sync(0xFFFFFFFFu, a0, o);
        if (lane == 0) g_e0[row] = frame[row] - a0 * INV_WSCALE;
    } else {
        int row = (b - 1024) * 8 + warp;     // 0..4095
        const uint4* w0 = (const uint4*)(g_W1f8 + (size_t)row * N2);
        const uint4* rp = (const uint4*)g_rh2;   // 256 uint4 = 2048 halves
        float a0 = 0.f;
        // 128 uint4 per row, 4 iters per lane
        #pragma unroll
        for (int i = 0; i < 4; i++) {
            int c = lane + i * 32;
            uint4 rq0 = __ldg(rp + 2 * c);
            uint4 rq1 = __ldg(rp + 2 * c + 1);
            dot16_f8(__ldg(w0 + c), rq0, rq1, a0);
        }
        #pragma unroll
        for (int o = 16; o; o >>= 1) a0 += __shfl_xor_sync(0xFFFFFFFFu, a0, o);
        if (lane == 0) g_e1[row] = g_rout1[row] - a0 * INV_WSCALE;
    }
}

// ---------------- per-step K2: transpose matvec partials -----------------------
// 32-row chunks, thread = 4 consecutive cols (one LDG.32 per row -> warp covers
// one full 128B line; STG.128 per thread -> warp stores 512B contiguous).
// Blocks [0,1024): W0 (4 colblocks x 256 chunks).
// Blocks [1024,1280): W1 (2 colblocks x 128 chunks).
__global__ void __launch_bounds__(256) k_transpose() {
    __shared__ __half2 s_eh[32];
    int tid = threadIdx.x;
    int b = blockIdx.x;

    const unsigned char* wmat;
    float* pbu;
    int col0, row0, chunk, ldw;
    if (b < 1024) {
        int colblock = b & 3;
        chunk = b >> 2;                      // 0..255
        col0 = colblock * 1024 + tid * 4;
        row0 = chunk * 32;
        if (tid < 32) s_eh[tid] = __float2half2_rn(g_e0[row0 + tid]);
        wmat = g_W0f8;
        pbu = g_pbu1;
        ldw = N1;
    } else {
        int b2 = b - 1024;                   // 0..255
        int colblock = b2 & 1;
        chunk = b2 >> 1;                     // 0..127
        col0 = colblock * 1024 + tid * 4;
        row0 = chunk * 32;
        if (tid < 32) s_eh[tid] = __float2half2_rn(g_e1[row0 + tid]);
        wmat = g_W1f8;
        pbu = g_pbu2;
        ldw = N2;
    }
    __syncthreads();

    const unsigned char* wbase = wmat + (size_t)row0 * ldw + col0;

    float f0 = 0.f, f1 = 0.f, f2 = 0.f, f3 = 0.f;
    #pragma unroll
    for (int seg = 0; seg < 2; seg++) {
        __half2 a01 = __float2half2_rn(0.0f);
        __half2 a23 = __float2half2_rn(0.0f);
        #pragma unroll
        for (int r = 0; r < 16; r++) {
            unsigned u = *reinterpret_cast<const unsigned*>(wbase + (size_t)(seg * 16 + r) * ldw);
            __half2 ev = s_eh[seg * 16 + r];
            __half2 a, bb;
            u32_to_2h2(u, a, bb);
            a01 = __hfma2(a, ev, a01);
            a23 = __hfma2(bb, ev, a23);
        }
        float2 x = __half22float2(a01);
        float2 y = __half22float2(a23);
        f0 += x.x; f1 += x.y; f2 += y.x; f3 += y.y;
    }

    *reinterpret_cast<float4*>(&pbu[(size_t)chunk * ldw + col0]) = make_float4(f0, f1, f2, f3);
}

// ---------------- per-step K3: deterministic reduce + state update -------------
// Block = 256 thr as (32 cols x 8 chunk-groups). Blocks [0,128): layer1 (32 cols
// each). Blocks [128,192): layer2.
__global__ void __launch_bounds__(256) k_update() {
    __shared__ float s[256];
    int b = blockIdx.x;
    int cx = threadIdx.x & 31;     // col within group
    int gy = threadIdx.x >> 5;     // chunk group 0..7
    if (b < 128) {
        int col = b * 32 + cx;
        float s0 = 0.f;
        // CH0 = 256 chunks -> 32 per group
        #pragma unroll 16
        for (int i = 0; i < 32; i++)
            s0 += g_pbu1[(size_t)(gy * 32 + i) * N1 + col];
        s[threadIdx.x] = s0;
        __syncthreads();
        if (gy == 0) {
            float tot = 0.f;
            #pragma unroll
            for (int g = 0; g < 8; g++) tot += s[g * 32 + cx];
            float bu1 = tot * INV_WSCALE;
            float na = g_ract1[col] + INF1 * (bu1 - g_e1[col]);
            g_ract1[col] = na;
            float ro = sigm3(na);
            g_rout1[col] = ro;
            g_rh1[col] = __float2half(ro);
        }
    } else {
        int col = (b - 128) * 32 + cx;
        float s0 = 0.f;
        // CH1 = 128 chunks -> 16 per group
        #pragma unroll 16
        for (int i = 0; i < 16; i++)
            s0 += g_pbu2[(size_t)(gy * 16 + i) * N2 + col];
        s[threadIdx.x] = s0;
        __syncthreads();
        if (gy == 0) {
            float tot = 0.f;
            #pragma unroll
            for (int g = 0; g < 8; g++) tot += s[g * 32 + cx];
            float bu2 = tot * INV_WSCALE;
            float na = g_ract2[col] + INF2 * bu2;
            g_ract2[col] = na;
            float ro = sigm3(na);
            g_rout2[col] = ro;
            g_rh2[col] = __float2half(ro);
        }
    }
}

// ---------------- output assembly ---------------------------------------------
__global__ void k_output(float* __restrict__ out) {
    int i = blockIdx.x * blockDim.x + threadIdx.x;
    if (i < N0) {
        out[i] = g_e0[i];
    } else if (i < N0 + N1) {
        out[i] = g_e1[i - N0];
    } else if (i < N0 + 2 * N1) {
        out[i] = g_rout1[i - N0 - N1];
    } else if (i < N0 + 2 * N1 + N2) {
        out[i] = g_rout2[i - N0 - 2 * N1];
    }
}

extern "C" void kernel_launch(void* const* d_in, const int* in_sizes, int n_in,
                              void* d_out, int out_size) {
    const float* frame = (const float*)d_in[0];
    const float* W0    = (const float*)d_in[1];
    const float* W1    = (const float*)d_in[2];
    float* out = (float*)d_out;

    const size_t totq = ((size_t)N0 * N1 + (size_t)N1 * N2) / 4;
    int cvt_blocks = (int)((totq + 255) / 256);
    k_convert<<<cvt_blocks, 256>>>(W0, W1);
    k_init<<<24, 256>>>();

    for (int t = 0; t < STEPS; t++) {
        k_forward<<<1536, 256>>>(frame);
        k_transpose<<<1280, 256>>>();
        k_update<<<192, 256>>>();
    }
    k_output<<<72, 256>>>(out);
}